// round 2
// baseline (speedup 1.0000x reference)
#include <cuda_runtime.h>
#include <math.h>

// Problem constants
#define NTOK 2048   // B*T
#define DIM  1024   // D
#define NE   16     // experts
#define NF   512    // F
#define NFS  2048   // shared F

// ---------------- scratch (static __device__ — no allocation) ----------------
__device__ float g_probs[NTOK * NE];          // softmax probs (for aux loss)
__device__ int   g_topk_idx[NTOK * 2];
__device__ float g_topk_w[NTOK * 2];          // normalized top-2 weights
__device__ float g_sgate[NTOK];               // sigmoid shared gate per token
__device__ int   g_counts[NE];
__device__ int   g_offsets[NE];
__device__ int   g_cursor[NE];
__device__ int   g_row2slot[NTOK * 2];        // grouped row -> (token*2 + k)
__device__ float g_H[(size_t)NTOK * 2 * NF];        // 8 MB  expert hidden
__device__ float g_partial[(size_t)NTOK * 2 * DIM]; // 16 MB per-slot expert out
__device__ float g_HS[(size_t)NTOK * NFS];          // 16 MB shared hidden
__device__ float g_SH[(size_t)NTOK * DIM];          // 8 MB  shared out

// ---------------- init: zero per-expert counts ----------------
__global__ void init_kernel() {
    if (threadIdx.x < NE) g_counts[threadIdx.x] = 0;
}

// ---------------- router: logits, softmax, top-2, sigmoid gate ----------------
__global__ void router_kernel(const float* __restrict__ x,
                              const float* __restrict__ rw,
                              const float* __restrict__ sgw) {
    const int t = blockIdx.x;
    const int tid = threadIdx.x;           // 128 threads
    const float* xr = x + (size_t)t * DIM;
    float acc[NE];
#pragma unroll
    for (int e = 0; e < NE; e++) acc[e] = 0.f;
    float sga = 0.f;
    for (int d = tid; d < DIM; d += 128) {
        float xv = xr[d];
        const float* r = rw + (size_t)d * NE;
#pragma unroll
        for (int e = 0; e < NE; e++) acc[e] = fmaf(xv, r[e], acc[e]);
        sga = fmaf(xv, sgw[d], sga);
    }
#pragma unroll
    for (int off = 16; off > 0; off >>= 1) {
#pragma unroll
        for (int e = 0; e < NE; e++)
            acc[e] += __shfl_down_sync(0xffffffffu, acc[e], off);
        sga += __shfl_down_sync(0xffffffffu, sga, off);
    }
    __shared__ float s[4][NE + 1];
    const int w = tid >> 5, l = tid & 31;
    if (l == 0) {
#pragma unroll
        for (int e = 0; e < NE; e++) s[w][e] = acc[e];
        s[w][NE] = sga;
    }
    __syncthreads();
    if (tid == 0) {
        float logits[NE];
#pragma unroll
        for (int e = 0; e < NE; e++)
            logits[e] = s[0][e] + s[1][e] + s[2][e] + s[3][e];
        float sg = s[0][NE] + s[1][NE] + s[2][NE] + s[3][NE];
        float mx = logits[0];
#pragma unroll
        for (int e = 1; e < NE; e++) mx = fmaxf(mx, logits[e]);
        float p[NE];
        float sum = 0.f;
#pragma unroll
        for (int e = 0; e < NE; e++) { p[e] = expf(logits[e] - mx); sum += p[e]; }
        float inv = 1.f / sum;
#pragma unroll
        for (int e = 0; e < NE; e++) { p[e] *= inv; g_probs[t * NE + e] = p[e]; }
        // top-2 (ties -> lowest index, matching lax.top_k)
        int i1 = 0; float v1 = p[0];
#pragma unroll
        for (int e = 1; e < NE; e++) if (p[e] > v1) { v1 = p[e]; i1 = e; }
        int i2 = -1; float v2 = -1.f;
#pragma unroll
        for (int e = 0; e < NE; e++)
            if (e != i1 && p[e] > v2) { v2 = p[e]; i2 = e; }
        float denom = fmaxf(v1 + v2, 1e-9f);
        g_topk_idx[t * 2 + 0] = i1;
        g_topk_idx[t * 2 + 1] = i2;
        g_topk_w[t * 2 + 0] = v1 / denom;
        g_topk_w[t * 2 + 1] = v2 / denom;
        g_sgate[t] = 1.f / (1.f + expf(-sg));
        atomicAdd(&g_counts[i1], 1);
        atomicAdd(&g_counts[i2], 1);
    }
}

// ---------------- prefix offsets + zero cursors ----------------
__global__ void prep_kernel() {
    if (threadIdx.x == 0) {
        int o = 0;
        for (int e = 0; e < NE; e++) {
            g_offsets[e] = o;
            o += g_counts[e];
            g_cursor[e] = 0;
        }
    }
}

// ---------------- scatter slots into per-expert groups ----------------
__global__ void scatter_kernel() {
    int s = blockIdx.x * blockDim.x + threadIdx.x;
    if (s >= NTOK * 2) return;
    int e = g_topk_idx[s];
    int pos = atomicAdd(&g_cursor[e], 1);
    g_row2slot[g_offsets[e] + pos] = s;
}

// ---------------- expert gate+up fused GEMM, silu(g)*u -> g_H ----------------
// C[M,N] = Xg[M,K] * W[N,K]^T per expert, dual-B (gate rows / up rows)
__global__ void __launch_bounds__(256) expert_gateup_kernel(
    const float* __restrict__ x, const float* __restrict__ gup) {
    const int e = blockIdx.z;
    const int cnt = g_counts[e];
    const int m0 = blockIdx.y * 64;
    if (m0 >= cnt) return;
    const int n0 = blockIdx.x * 64;
    const int off = g_offsets[e];
    __shared__ __align__(16) float As[16][68];
    __shared__ __align__(16) float Bg[16][68];
    __shared__ __align__(16) float Bu[16][68];
    __shared__ int tok[64];
    const int tid = threadIdx.x;
    if (tid < 64) {
        int r = m0 + tid;
        tok[tid] = (r < cnt) ? (g_row2slot[off + r] >> 1) : -1;
    }
    __syncthreads();
    float accG[4][4] = {};
    float accU[4][4] = {};
    const int ty = tid >> 4, tx = tid & 15;
    const float* wg = gup + ((size_t)e * 1024 + n0) * (size_t)DIM;
    const float* wu = gup + ((size_t)e * 1024 + 512 + n0) * (size_t)DIM;
    for (int k0 = 0; k0 < DIM; k0 += 16) {
#pragma unroll
        for (int i = tid; i < 1024; i += 256) {
            int m = i >> 4, k = i & 15;
            int t = tok[m];
            As[k][m] = (t >= 0) ? x[(size_t)t * DIM + k0 + k] : 0.f;
            Bg[k][m] = wg[(size_t)m * DIM + k0 + k];
            Bu[k][m] = wu[(size_t)m * DIM + k0 + k];
        }
        __syncthreads();
#pragma unroll
        for (int k = 0; k < 16; k++) {
            const float4 av  = *reinterpret_cast<const float4*>(&As[k][ty * 4]);
            const float4 bgv = *reinterpret_cast<const float4*>(&Bg[k][tx * 4]);
            const float4 buv = *reinterpret_cast<const float4*>(&Bu[k][tx * 4]);
            const float a[4]  = {av.x, av.y, av.z, av.w};
            const float bg[4] = {bgv.x, bgv.y, bgv.z, bgv.w};
            const float bu[4] = {buv.x, buv.y, buv.z, buv.w};
#pragma unroll
            for (int i = 0; i < 4; i++)
#pragma unroll
                for (int j = 0; j < 4; j++) {
                    accG[i][j] = fmaf(a[i], bg[j], accG[i][j]);
                    accU[i][j] = fmaf(a[i], bu[j], accU[i][j]);
                }
        }
        __syncthreads();
    }
#pragma unroll
    for (int i = 0; i < 4; i++) {
        int r = m0 + ty * 4 + i;
        if (r >= cnt) continue;
        size_t base = (size_t)(off + r) * NF + n0 + tx * 4;
#pragma unroll
        for (int j = 0; j < 4; j++) {
            float g = accG[i][j];
            float h = (g / (1.f + expf(-g))) * accU[i][j];  // silu(g)*u
            g_H[base + j] = h;
        }
    }
}

// ---------------- expert down GEMM, scale by topk weight -> g_partial ----------------
__global__ void __launch_bounds__(256) expert_down_kernel(
    const float* __restrict__ down) {
    const int e = blockIdx.z;
    const int cnt = g_counts[e];
    const int m0 = blockIdx.y * 64;
    if (m0 >= cnt) return;
    const int n0 = blockIdx.x * 64;
    const int off = g_offsets[e];
    __shared__ __align__(16) float As[16][68];
    __shared__ __align__(16) float Bs[16][68];
    const int tid = threadIdx.x;
    float acc[4][4] = {};
    const int ty = tid >> 4, tx = tid & 15;
    const float* wd = down + ((size_t)e * DIM + n0) * (size_t)NF;
    for (int k0 = 0; k0 < NF; k0 += 16) {
#pragma unroll
        for (int i = tid; i < 1024; i += 256) {
            int m = i >> 4, k = i & 15;
            int r = m0 + m;
            As[k][m] = (r < cnt) ? g_H[(size_t)(off + r) * NF + k0 + k] : 0.f;
            Bs[k][m] = wd[(size_t)m * NF + k0 + k];
        }
        __syncthreads();
#pragma unroll
        for (int k = 0; k < 16; k++) {
            const float4 av = *reinterpret_cast<const float4*>(&As[k][ty * 4]);
            const float4 bv = *reinterpret_cast<const float4*>(&Bs[k][tx * 4]);
            const float a[4] = {av.x, av.y, av.z, av.w};
            const float b[4] = {bv.x, bv.y, bv.z, bv.w};
#pragma unroll
            for (int i = 0; i < 4; i++)
#pragma unroll
                for (int j = 0; j < 4; j++)
                    acc[i][j] = fmaf(a[i], b[j], acc[i][j]);
        }
        __syncthreads();
    }
#pragma unroll
    for (int i = 0; i < 4; i++) {
        int r = m0 + ty * 4 + i;
        if (r >= cnt) continue;
        int slot = g_row2slot[off + r];
        float wkt = g_topk_w[slot];
        size_t base = (size_t)slot * DIM + n0 + tx * 4;
#pragma unroll
        for (int j = 0; j < 4; j++) g_partial[base + j] = wkt * acc[i][j];
    }
}

// ---------------- shared expert gate+up fused GEMM (NN layout) ----------------
__global__ void __launch_bounds__(256) shared_gu_kernel(
    const float* __restrict__ x, const float* __restrict__ wgate,
    const float* __restrict__ wup) {
    const int m0 = blockIdx.y * 64;
    const int n0 = blockIdx.x * 64;
    __shared__ __align__(16) float As[16][68];
    __shared__ __align__(16) float Bg[16][68];
    __shared__ __align__(16) float Bu[16][68];
    const int tid = threadIdx.x;
    float accG[4][4] = {};
    float accU[4][4] = {};
    const int ty = tid >> 4, tx = tid & 15;
    for (int k0 = 0; k0 < DIM; k0 += 16) {
#pragma unroll
        for (int i = tid; i < 1024; i += 256) {
            int m = i >> 4, k = i & 15;
            As[k][m] = x[(size_t)(m0 + m) * DIM + k0 + k];
        }
#pragma unroll
        for (int i = tid; i < 1024; i += 256) {
            int n = i & 63, k = i >> 6;
            Bg[k][n] = wgate[(size_t)(k0 + k) * NFS + n0 + n];
            Bu[k][n] = wup[(size_t)(k0 + k) * NFS + n0 + n];
        }
        __syncthreads();
#pragma unroll
        for (int k = 0; k < 16; k++) {
            const float4 av  = *reinterpret_cast<const float4*>(&As[k][ty * 4]);
            const float4 bgv = *reinterpret_cast<const float4*>(&Bg[k][tx * 4]);
            const float4 buv = *reinterpret_cast<const float4*>(&Bu[k][tx * 4]);
            const float a[4]  = {av.x, av.y, av.z, av.w};
            const float bg[4] = {bgv.x, bgv.y, bgv.z, bgv.w};
            const float bu[4] = {buv.x, buv.y, buv.z, buv.w};
#pragma unroll
            for (int i = 0; i < 4; i++)
#pragma unroll
                for (int j = 0; j < 4; j++) {
                    accG[i][j] = fmaf(a[i], bg[j], accG[i][j]);
                    accU[i][j] = fmaf(a[i], bu[j], accU[i][j]);
                }
        }
        __syncthreads();
    }
#pragma unroll
    for (int i = 0; i < 4; i++) {
        size_t base = (size_t)(m0 + ty * 4 + i) * NFS + n0 + tx * 4;
#pragma unroll
        for (int j = 0; j < 4; j++) {
            float g = accG[i][j];
            g_HS[base + j] = (g / (1.f + expf(-g))) * accU[i][j];
        }
    }
}

// ---------------- shared expert down GEMM (NN layout) ----------------
__global__ void __launch_bounds__(256) shared_down_kernel(
    const float* __restrict__ wdown) {
    const int m0 = blockIdx.y * 64;
    const int n0 = blockIdx.x * 64;
    __shared__ __align__(16) float As[16][68];
    __shared__ __align__(16) float Bs[16][68];
    const int tid = threadIdx.x;
    float acc[4][4] = {};
    const int ty = tid >> 4, tx = tid & 15;
    for (int k0 = 0; k0 < NFS; k0 += 16) {
#pragma unroll
        for (int i = tid; i < 1024; i += 256) {
            int m = i >> 4, k = i & 15;
            As[k][m] = g_HS[(size_t)(m0 + m) * NFS + k0 + k];
        }
#pragma unroll
        for (int i = tid; i < 1024; i += 256) {
            int n = i & 63, k = i >> 6;
            Bs[k][n] = wdown[(size_t)(k0 + k) * DIM + n0 + n];
        }
        __syncthreads();
#pragma unroll
        for (int k = 0; k < 16; k++) {
            const float4 av = *reinterpret_cast<const float4*>(&As[k][ty * 4]);
            const float4 bv = *reinterpret_cast<const float4*>(&Bs[k][tx * 4]);
            const float a[4] = {av.x, av.y, av.z, av.w};
            const float b[4] = {bv.x, bv.y, bv.z, bv.w};
#pragma unroll
            for (int i = 0; i < 4; i++)
#pragma unroll
                for (int j = 0; j < 4; j++)
                    acc[i][j] = fmaf(a[i], b[j], acc[i][j]);
        }
        __syncthreads();
    }
#pragma unroll
    for (int i = 0; i < 4; i++) {
        size_t base = (size_t)(m0 + ty * 4 + i) * DIM + n0 + tx * 4;
#pragma unroll
        for (int j = 0; j < 4; j++) g_SH[base + j] = acc[i][j];
    }
}

// ---------------- combine: moe partials + sigmoid-gated shared ----------------
__global__ void combine_kernel(float* __restrict__ out) {
    int i = blockIdx.x * blockDim.x + threadIdx.x;
    if (i >= NTOK * DIM) return;
    int t = i >> 10;                 // DIM = 1024
    int d = i & (DIM - 1);
    float p0 = g_partial[(size_t)(t * 2) * DIM + d];
    float p1 = g_partial[(size_t)(t * 2 + 1) * DIM + d];
    out[i] = (p0 + p1) + g_sgate[t] * g_SH[i];
}

// ---------------- aux loss: deterministic fixed-order reduction ----------------
__global__ void aux_kernel(float* __restrict__ out_aux) {
    __shared__ float sload[NE];
    const int w = threadIdx.x >> 5, l = threadIdx.x & 31;
    if (w < NE) {
        float a = 0.f;
        for (int t = l; t < NTOK; t += 32) a += g_probs[t * NE + w];
#pragma unroll
        for (int off = 16; off > 0; off >>= 1)
            a += __shfl_down_sync(0xffffffffu, a, off);
        if (l == 0) sload[w] = a * (1.f / NTOK);
    }
    __syncthreads();
    if (threadIdx.x == 0) {
        float aux = 0.f;
#pragma unroll
        for (int e = 0; e < NE; e++) {
            float dlt = sload[e] - (1.f / NE);
            aux += dlt * dlt;
        }
        out_aux[0] = 0.001f * aux;
    }
}

// ---------------- launch ----------------
extern "C" void kernel_launch(void* const* d_in, const int* in_sizes, int n_in,
                              void* d_out, int out_size) {
    const float* x    = (const float*)d_in[0];  // [2,1024,1024]
    const float* gup  = (const float*)d_in[1];  // [16,1024,1024]
    const float* down = (const float*)d_in[2];  // [16,1024,512]
    const float* rw   = (const float*)d_in[3];  // [1024,16]
    const float* shg  = (const float*)d_in[4];  // [1024,2048]
    const float* shu  = (const float*)d_in[5];  // [1024,2048]
    const float* shd  = (const float*)d_in[6];  // [2048,1024]
    const float* sgw  = (const float*)d_in[7];  // [1024,1]
    float* out = (float*)d_out;

    init_kernel<<<1, 32>>>();
    router_kernel<<<NTOK, 128>>>(x, rw, sgw);
    prep_kernel<<<1, 32>>>();
    scatter_kernel<<<(NTOK * 2 + 255) / 256, 256>>>();
    expert_gateup_kernel<<<dim3(NF / 64, NTOK / 64, NE), 256>>>(x, gup);
    expert_down_kernel<<<dim3(DIM / 64, NTOK / 64, NE), 256>>>(down);
    shared_gu_kernel<<<dim3(NFS / 64, NTOK / 64), 256>>>(x, shg, shu);
    shared_down_kernel<<<dim3(DIM / 64, NTOK / 64), 256>>>(shd);
    combine_kernel<<<(NTOK * DIM + 255) / 256, 256>>>(out);
    if (out_size > NTOK * DIM) aux_kernel<<<1, 512>>>(out + NTOK * DIM);
}